// round 6
// baseline (speedup 1.0000x reference)
#include <cuda_runtime.h>
#include <cuda_bf16.h>
#include <cstdint>

// Problem constants
#define NN   50000
#define EE   800000
#define FIN  128
#define FHID 128
#define FOUT 64

// ---------------------------------------------------------------------------
// Scratch (static __device__ arrays — no allocation allowed)
// ---------------------------------------------------------------------------
__device__ float g_h[(size_t)NN * FHID];    // h1_raw = x@W1   (unscaled)
__device__ float g_agg[(size_t)NN * FHID];  // h = relu(dis*(sum)+b1)
__device__ float g_h2[(size_t)NN * FOUT];   // h2_raw = h@W2   (unscaled)
__device__ int   g_deg[NN];                 // in-degree histogram
__device__ float g_dis[NN];                 // (deg+1)^-1/2
__device__ int   g_starts[NN + 1];          // CSR row starts
__device__ int   g_cursor[NN];              // atomic fill cursors
__device__ int   g_csr_row[EE];             // source node per CSR slot
__device__ int   g_blocksum[64];            // per-block degree sums

// ---------------------------------------------------------------------------
// PTX helpers
// ---------------------------------------------------------------------------
__device__ __forceinline__ uint32_t smem_u32(const void* p) {
    return (uint32_t)__cvta_generic_to_shared(p);
}

__device__ __forceinline__ void ldmat_x4(uint32_t& r0, uint32_t& r1, uint32_t& r2, uint32_t& r3,
                                         uint32_t addr) {
    asm volatile("ldmatrix.sync.aligned.m8n8.x4.shared.b16 {%0,%1,%2,%3}, [%4];"
                 : "=r"(r0), "=r"(r1), "=r"(r2), "=r"(r3) : "r"(addr));
}
__device__ __forceinline__ void ldmat_x4_t(uint32_t& r0, uint32_t& r1, uint32_t& r2, uint32_t& r3,
                                           uint32_t addr) {
    asm volatile("ldmatrix.sync.aligned.m8n8.x4.trans.shared.b16 {%0,%1,%2,%3}, [%4];"
                 : "=r"(r0), "=r"(r1), "=r"(r2), "=r"(r3) : "r"(addr));
}

__device__ __forceinline__ void mma_bf16(float* d, const uint32_t* a, uint32_t b0, uint32_t b1) {
    asm volatile(
        "mma.sync.aligned.m16n8k16.row.col.f32.bf16.bf16.f32 "
        "{%0,%1,%2,%3}, {%4,%5,%6,%7}, {%8,%9}, {%0,%1,%2,%3};"
        : "+f"(d[0]), "+f"(d[1]), "+f"(d[2]), "+f"(d[3])
        : "r"(a[0]), "r"(a[1]), "r"(a[2]), "r"(a[3]), "r"(b0), "r"(b1));
}

// pack two fp32 into bf16x2 (hi) and residual bf16x2 (lo)
__device__ __forceinline__ void split2(float v0, float v1, uint32_t& hi, uint32_t& lo) {
    __nv_bfloat16 h0 = __float2bfloat16_rn(v0);
    __nv_bfloat16 h1 = __float2bfloat16_rn(v1);
    __nv_bfloat16 l0 = __float2bfloat16_rn(v0 - __bfloat162float(h0));
    __nv_bfloat16 l1 = __float2bfloat16_rn(v1 - __bfloat162float(h1));
    __nv_bfloat162 ph = {h0, h1}, pl = {l0, l1};
    hi = *(uint32_t*)&ph;
    lo = *(uint32_t*)&pl;
}

// Degree histogram
__global__ void count_deg_kernel(const int* __restrict__ col, int* __restrict__ deg, int e) {
    int i = blockIdx.x * blockDim.x + threadIdx.x;
    if (i < e) atomicAdd(&deg[col[i]], 1);
}

// ---------------------------------------------------------------------------
// scan1: per-block (1024 elems) degree totals; also computes dis = rsqrt(deg+1)
// ---------------------------------------------------------------------------
__global__ void __launch_bounds__(256)
scan1_kernel(const int* __restrict__ deg, int* __restrict__ blocksum,
             float* __restrict__ dis, int n) {
    __shared__ int wsum[8];
    int t = threadIdx.x, b = blockIdx.x;
    int base = b * 1024 + t * 4;
    int s = 0;
#pragma unroll
    for (int j = 0; j < 4; j++) {
        int idx = base + j;
        int d = (idx < n) ? deg[idx] : 0;
        s += d;
        if (idx < n) dis[idx] = rsqrtf((float)d + 1.0f);
    }
#pragma unroll
    for (int o = 16; o > 0; o >>= 1) s += __shfl_down_sync(0xffffffffu, s, o);
    if ((t & 31) == 0) wsum[t >> 5] = s;
    __syncthreads();
    if (t == 0) {
        int tot = 0;
#pragma unroll
        for (int w = 0; w < 8; w++) tot += wsum[w];
        blocksum[b] = tot;
    }
}

// ---------------------------------------------------------------------------
// scan3: per-block exclusive scan; block offset computed by PARALLEL reduce
// of the (<=64) block sums (was a serial thread-0 loop = 5.3us of latency).
// ---------------------------------------------------------------------------
__global__ void __launch_bounds__(256)
scan3_kernel(const int* __restrict__ deg, const int* __restrict__ blocksum,
             int* __restrict__ starts, int* __restrict__ cursor, int n, int nblk) {
    __shared__ int wtot[8];
    __shared__ int sh_off[2];   // partial sums of blocksum[0..b) from warps 0,1
    __shared__ int sh_tot[2];   // partial sums of blocksum[0..nblk) (last block)
    int t = threadIdx.x, b = blockIdx.x;
    int lane = t & 31, wid = t >> 5;

    // parallel block-offset: threads 0..63 each own one predecessor block sum
    if (t < 64) {
        int v = (t < nblk) ? blocksum[t] : 0;
        int voff = (t < b) ? v : 0;
#pragma unroll
        for (int o = 16; o > 0; o >>= 1) {
            voff += __shfl_down_sync(0xffffffffu, voff, o);
            v    += __shfl_down_sync(0xffffffffu, v, o);
        }
        if (lane == 0) { sh_off[wid] = voff; sh_tot[wid] = v; }
    }

    int base = b * 1024 + t * 4;
    int v4[4];
#pragma unroll
    for (int j = 0; j < 4; j++) {
        int idx = base + j;
        v4[j] = (idx < n) ? deg[idx] : 0;
    }
    int tsum = v4[0] + v4[1] + v4[2] + v4[3];
    int incl = tsum;
#pragma unroll
    for (int o = 1; o < 32; o <<= 1) {
        int u = __shfl_up_sync(0xffffffffu, incl, o);
        if (lane >= o) incl += u;
    }
    if (lane == 31) wtot[wid] = incl;
    __syncthreads();

    int boff = sh_off[0] + sh_off[1];
    if (b == nblk - 1 && t == 0) starts[n] = sh_tot[0] + sh_tot[1];

    int woff = 0;
#pragma unroll
    for (int w = 0; w < 8; w++) woff += (w < wid) ? wtot[w] : 0;
    int excl = boff + woff + incl - tsum;
#pragma unroll
    for (int j = 0; j < 4; j++) {
        int idx = base + j;
        if (idx < n) { starts[idx] = excl; cursor[idx] = excl; }
        excl += v4[j];
    }
}

// CSR fill
__global__ void fill_kernel(const int* __restrict__ row, const int* __restrict__ col,
                            int* __restrict__ cursor, int* __restrict__ csr_row, int e) {
    int i = blockIdx.x * blockDim.x + threadIdx.x;
    if (i < e) {
        int slot = atomicAdd(&cursor[col[i]], 1);
        csr_row[slot] = row[i];
    }
}

// ---------------------------------------------------------------------------
// Tensor-core GEMM via split-bf16 (3xBF16 ~ fp32 precision):
//   out[N, F] = x[N, 128] @ W[128, F]       (pure GEMM, graph-independent)
// ---------------------------------------------------------------------------
template <int F>
__global__ void __launch_bounds__(256)
gemm_tc_kernel(const float* __restrict__ x, const float* __restrict__ W,
               float* __restrict__ out, int nrows) {
    constexpr int BM   = 128;
    constexpr int KT   = 64;
    constexpr int NT   = F / 8;
    constexpr int ASTR = KT + 8;
    constexpr int WSTR = F + 8;

    extern __shared__ __nv_bfloat16 smem[];
    __nv_bfloat16* Ahi = smem;
    __nv_bfloat16* Alo = Ahi + BM * ASTR;
    __nv_bfloat16* Whi = Alo + BM * ASTR;
    __nv_bfloat16* Wlo = Whi + KT * WSTR;

    const int tid  = threadIdx.x;
    const int lane = tid & 31;
    const int wr   = tid >> 5;
    const int row0 = blockIdx.x * BM;

    float acc[NT][4];
#pragma unroll
    for (int nt = 0; nt < NT; nt++)
#pragma unroll
        for (int j = 0; j < 4; j++) acc[nt][j] = 0.f;

    const int mat  = lane >> 3;
    const int mrow = lane & 7;

    for (int kt = 0; kt < FIN; kt += KT) {
        {
            constexpr int NV = (BM * KT) / 4;
#pragma unroll
            for (int p = tid; p < NV; p += 256) {
                int r  = p / (KT / 4);
                int kq = (p % (KT / 4)) * 4;
                float4 v;
                int grow = row0 + r;
                if (grow < nrows)
                    v = *(const float4*)(x + (size_t)grow * FIN + kt + kq);
                else
                    v = make_float4(0.f, 0.f, 0.f, 0.f);
                uint32_t h01, l01, h23, l23;
                split2(v.x, v.y, h01, l01);
                split2(v.z, v.w, h23, l23);
                *(uint32_t*)(Ahi + r * ASTR + kq)     = h01;
                *(uint32_t*)(Ahi + r * ASTR + kq + 2) = h23;
                *(uint32_t*)(Alo + r * ASTR + kq)     = l01;
                *(uint32_t*)(Alo + r * ASTR + kq + 2) = l23;
            }
        }
        {
            constexpr int NV = (KT * F) / 4;
#pragma unroll
            for (int p = tid; p < NV; p += 256) {
                int k = p / (F / 4);
                int c = (p % (F / 4)) * 4;
                float4 v = *(const float4*)(W + (size_t)(kt + k) * F + c);
                uint32_t h01, l01, h23, l23;
                split2(v.x, v.y, h01, l01);
                split2(v.z, v.w, h23, l23);
                *(uint32_t*)(Whi + k * WSTR + c)     = h01;
                *(uint32_t*)(Whi + k * WSTR + c + 2) = h23;
                *(uint32_t*)(Wlo + k * WSTR + c)     = l01;
                *(uint32_t*)(Wlo + k * WSTR + c + 2) = l23;
            }
        }
        __syncthreads();

#pragma unroll
        for (int ks = 0; ks < KT / 16; ks++) {
            uint32_t ah[4], al[4];
            {
                int arow = wr * 16 + (mat & 1) * 8 + mrow;
                int acol = ks * 16 + (mat >> 1) * 8;
                uint32_t a_hi = smem_u32(Ahi + arow * ASTR + acol);
                uint32_t a_lo = smem_u32(Alo + arow * ASTR + acol);
                ldmat_x4(ah[0], ah[1], ah[2], ah[3], a_hi);
                ldmat_x4(al[0], al[1], al[2], al[3], a_lo);
            }
#pragma unroll
            for (int nt2 = 0; nt2 < NT / 2; nt2++) {
                int krow = ks * 16 + (mat & 1) * 8 + mrow;
                int ncol = nt2 * 16 + (mat >> 1) * 8;
                uint32_t w_hi = smem_u32(Whi + krow * WSTR + ncol);
                uint32_t w_lo = smem_u32(Wlo + krow * WSTR + ncol);
                uint32_t bh[4], bl[4];
                ldmat_x4_t(bh[0], bh[1], bh[2], bh[3], w_hi);
                ldmat_x4_t(bl[0], bl[1], bl[2], bl[3], w_lo);
                mma_bf16(acc[2 * nt2], ah, bh[0], bh[1]);
                mma_bf16(acc[2 * nt2], ah, bl[0], bl[1]);
                mma_bf16(acc[2 * nt2], al, bh[0], bh[1]);
                mma_bf16(acc[2 * nt2 + 1], ah, bh[2], bh[3]);
                mma_bf16(acc[2 * nt2 + 1], ah, bl[2], bl[3]);
                mma_bf16(acc[2 * nt2 + 1], al, bh[2], bh[3]);
            }
        }
        __syncthreads();
    }

    {
        int r0 = row0 + wr * 16 + (lane >> 2);
        int r1 = r0 + 8;
        int cbase = (lane & 3) * 2;
#pragma unroll
        for (int nt = 0; nt < NT; nt++) {
            int c = nt * 8 + cbase;
            if (r0 < nrows)
                *(float2*)(out + (size_t)r0 * F + c) = make_float2(acc[nt][0], acc[nt][1]);
            if (r1 < nrows)
                *(float2*)(out + (size_t)r1 * F + c) = make_float2(acc[nt][2], acc[nt][3]);
        }
    }
}

// ---------------------------------------------------------------------------
// CSR segment-sum aggregate with dis folded at the gather, 4-way ILP:
//   out[c] = act( dis[c] * ( dis[c]*h[c] + sum_e dis[r_e]*h[r_e] ) + bias )
// ---------------------------------------------------------------------------
template <int F, bool RELU>
__global__ void __launch_bounds__(256)
aggregate_kernel(const float* __restrict__ hs,
                 const int* __restrict__ csr_row, const int* __restrict__ starts,
                 const float* __restrict__ dis, const float* __restrict__ bias,
                 float* __restrict__ out, int n) {
    constexpr int LPN = F / 4;
    const int gtid = blockIdx.x * blockDim.x + threadIdx.x;
    const int node = gtid / LPN;
    const int sub  = gtid % LPN;
    if (node >= n) return;

    const int beg = __ldg(starts + node);
    const int end = __ldg(starts + node + 1);
    const float d = __ldg(dis + node);

    // self loop: dis[node] * h[node]
    float4 a0 = *(const float4*)(hs + (size_t)node * F + sub * 4);
    a0.x *= d; a0.y *= d; a0.z *= d; a0.w *= d;
    float4 a1 = make_float4(0.f, 0.f, 0.f, 0.f);
    float4 a2 = make_float4(0.f, 0.f, 0.f, 0.f);
    float4 a3 = make_float4(0.f, 0.f, 0.f, 0.f);

    int e = beg;
    for (; e + 3 < end; e += 4) {
        int r0 = __ldg(csr_row + e);
        int r1 = __ldg(csr_row + e + 1);
        int r2 = __ldg(csr_row + e + 2);
        int r3 = __ldg(csr_row + e + 3);
        float d0 = __ldg(dis + r0);
        float d1 = __ldg(dis + r1);
        float d2 = __ldg(dis + r2);
        float d3 = __ldg(dis + r3);
        float4 v0 = *(const float4*)(hs + (size_t)r0 * F + sub * 4);
        float4 v1 = *(const float4*)(hs + (size_t)r1 * F + sub * 4);
        float4 v2 = *(const float4*)(hs + (size_t)r2 * F + sub * 4);
        float4 v3 = *(const float4*)(hs + (size_t)r3 * F + sub * 4);
        a0.x += v0.x * d0; a0.y += v0.y * d0; a0.z += v0.z * d0; a0.w += v0.w * d0;
        a1.x += v1.x * d1; a1.y += v1.y * d1; a1.z += v1.z * d1; a1.w += v1.w * d1;
        a2.x += v2.x * d2; a2.y += v2.y * d2; a2.z += v2.z * d2; a2.w += v2.w * d2;
        a3.x += v3.x * d3; a3.y += v3.y * d3; a3.z += v3.z * d3; a3.w += v3.w * d3;
    }
    for (; e < end; e++) {
        int r0 = __ldg(csr_row + e);
        float d0 = __ldg(dis + r0);
        float4 v0 = *(const float4*)(hs + (size_t)r0 * F + sub * 4);
        a0.x += v0.x * d0; a0.y += v0.y * d0; a0.z += v0.z * d0; a0.w += v0.w * d0;
    }

    float4 bv = *(const float4*)(bias + sub * 4);
    float4 o;
    o.x = (a0.x + a1.x + a2.x + a3.x) * d + bv.x;
    o.y = (a0.y + a1.y + a2.y + a3.y) * d + bv.y;
    o.z = (a0.z + a1.z + a2.z + a3.z) * d + bv.z;
    o.w = (a0.w + a1.w + a2.w + a3.w) * d + bv.w;
    if (RELU) {
        o.x = fmaxf(o.x, 0.f); o.y = fmaxf(o.y, 0.f);
        o.z = fmaxf(o.z, 0.f); o.w = fmaxf(o.w, 0.f);
    }
    *(float4*)(out + (size_t)node * F + sub * 4) = o;
}

// ---------------------------------------------------------------------------
// Launch
// ---------------------------------------------------------------------------
extern "C" void kernel_launch(void* const* d_in, const int* in_sizes, int n_in,
                              void* d_out, int out_size) {
    const float* x  = (const float*)d_in[0];
    const int*   ei = (const int*)d_in[1];
    const float* W1 = (const float*)d_in[2];
    const float* b1 = (const float*)d_in[3];
    const float* W2 = (const float*)d_in[4];
    const float* b2 = (const float*)d_in[5];
    float* out = (float*)d_out;

    const int* row = ei;
    const int* col = ei + EE;

    constexpr int SMEM1 = (128 * 72 * 2 + 64 * 136 * 2) * 2;  // F=128
    constexpr int SMEM2 = (128 * 72 * 2 + 64 * 72 * 2) * 2;   // F=64

    static float *p_h = nullptr, *p_agg = nullptr, *p_h2 = nullptr, *p_dis = nullptr;
    static int *p_deg = nullptr, *p_starts = nullptr, *p_cursor = nullptr,
               *p_csr = nullptr, *p_bsum = nullptr;
    static cudaStream_t s_side = nullptr;
    static cudaEvent_t s_fork = nullptr, s_join = nullptr;
    if (!p_h) {
        cudaGetSymbolAddress((void**)&p_h,      g_h);
        cudaGetSymbolAddress((void**)&p_agg,    g_agg);
        cudaGetSymbolAddress((void**)&p_h2,     g_h2);
        cudaGetSymbolAddress((void**)&p_dis,    g_dis);
        cudaGetSymbolAddress((void**)&p_deg,    g_deg);
        cudaGetSymbolAddress((void**)&p_starts, g_starts);
        cudaGetSymbolAddress((void**)&p_cursor, g_cursor);
        cudaGetSymbolAddress((void**)&p_csr,    g_csr_row);
        cudaGetSymbolAddress((void**)&p_bsum,   g_blocksum);
        cudaFuncSetAttribute(gemm_tc_kernel<128>,
                             cudaFuncAttributeMaxDynamicSharedMemorySize, SMEM1);
        cudaFuncSetAttribute(gemm_tc_kernel<64>,
                             cudaFuncAttributeMaxDynamicSharedMemorySize, SMEM2);
        cudaStreamCreateWithFlags(&s_side, cudaStreamNonBlocking);
        cudaEventCreateWithFlags(&s_fork, cudaEventDisableTiming);
        cudaEventCreateWithFlags(&s_join, cudaEventDisableTiming);
    }

    const int NBLK = (NN + 1023) / 1024;   // 49
    const int GBLK = (NN + 127) / 128;     // 391

    // ---- fork: CSR/degree chain on side stream (independent of GEMM1) ----
    cudaEventRecord(s_fork, 0);
    cudaStreamWaitEvent(s_side, s_fork, 0);
    cudaMemsetAsync(p_deg, 0, (size_t)NN * sizeof(int), s_side);       // memset node
    count_deg_kernel<<<(EE + 255) / 256, 256, 0, s_side>>>(col, p_deg, EE);   // launch 1
    scan1_kernel<<<NBLK, 256, 0, s_side>>>(p_deg, p_bsum, p_dis, NN);         // launch 2
    scan3_kernel<<<NBLK, 256, 0, s_side>>>(p_deg, p_bsum, p_starts, p_cursor, NN, NBLK); // 3

    // ---- main stream: layer 1 GEMM (pure, h1_raw = x@W1) — launch 4 ----
    gemm_tc_kernel<128><<<GBLK, 256, SMEM1>>>(x, W1, p_h, NN);

    fill_kernel<<<(EE + 255) / 256, 256, 0, s_side>>>(row, col, p_cursor, p_csr, EE); // 5
    cudaEventRecord(s_join, s_side);

    // ---- join: aggregates need CSR + dis ----
    cudaStreamWaitEvent(0, s_join, 0);

    // ---- layer 1 aggregate -> g_agg = h ----
    {
        long long threads = (long long)NN * 32;
        aggregate_kernel<128, true><<<(int)((threads + 255) / 256), 256>>>(
            p_h, p_csr, p_starts, p_dis, b1, p_agg, NN);
    }

    // ---- layer 2: GEMM (h2_raw = h@W2) ----
    gemm_tc_kernel<64><<<GBLK, 256, SMEM2>>>(p_agg, W2, p_h2, NN);

    // ---- layer 2 aggregate -> d_out ----
    {
        long long threads = (long long)NN * 16;
        aggregate_kernel<64, false><<<(int)((threads + 255) / 256), 256>>>(
            p_h2, p_csr, p_starts, p_dis, b2, out, NN);
    }
}

// round 7
// speedup vs baseline: 1.1134x; 1.1134x over previous
#include <cuda_runtime.h>
#include <cuda_bf16.h>
#include <cstdint>

// Problem constants
#define NN   50000
#define EE   800000
#define FIN  128
#define FHID 128
#define FOUT 64

// ---------------------------------------------------------------------------
// Scratch (static __device__ arrays — no allocation allowed)
// ---------------------------------------------------------------------------
__device__ float g_h[(size_t)NN * FHID];    // hs1 = (x@W1)*dis
__device__ float g_agg[(size_t)NN * FHID];  // h = relu(dis*(sum)+b1)
__device__ float g_h2[(size_t)NN * FOUT];   // hs2 = (h@W2)*dis
__device__ int   g_deg[NN];                 // in-degree histogram
__device__ float g_dis[NN];                 // (deg+1)^-1/2
__device__ int   g_starts[NN + 1];          // CSR row starts
__device__ int   g_cursor[NN];              // atomic fill cursors
__device__ int   g_csr_row[EE];             // source node per CSR slot
__device__ int   g_blocksum[64];            // per-block degree sums

// ---------------------------------------------------------------------------
// PTX helpers
// ---------------------------------------------------------------------------
__device__ __forceinline__ uint32_t smem_u32(const void* p) {
    return (uint32_t)__cvta_generic_to_shared(p);
}

__device__ __forceinline__ void ldmat_x4(uint32_t& r0, uint32_t& r1, uint32_t& r2, uint32_t& r3,
                                         uint32_t addr) {
    asm volatile("ldmatrix.sync.aligned.m8n8.x4.shared.b16 {%0,%1,%2,%3}, [%4];"
                 : "=r"(r0), "=r"(r1), "=r"(r2), "=r"(r3) : "r"(addr));
}
__device__ __forceinline__ void ldmat_x4_t(uint32_t& r0, uint32_t& r1, uint32_t& r2, uint32_t& r3,
                                           uint32_t addr) {
    asm volatile("ldmatrix.sync.aligned.m8n8.x4.trans.shared.b16 {%0,%1,%2,%3}, [%4];"
                 : "=r"(r0), "=r"(r1), "=r"(r2), "=r"(r3) : "r"(addr));
}

__device__ __forceinline__ void mma_bf16(float* d, const uint32_t* a, uint32_t b0, uint32_t b1) {
    asm volatile(
        "mma.sync.aligned.m16n8k16.row.col.f32.bf16.bf16.f32 "
        "{%0,%1,%2,%3}, {%4,%5,%6,%7}, {%8,%9}, {%0,%1,%2,%3};"
        : "+f"(d[0]), "+f"(d[1]), "+f"(d[2]), "+f"(d[3])
        : "r"(a[0]), "r"(a[1]), "r"(a[2]), "r"(a[3]), "r"(b0), "r"(b1));
}

// pack two fp32 into bf16x2 (hi) and residual bf16x2 (lo)
__device__ __forceinline__ void split2(float v0, float v1, uint32_t& hi, uint32_t& lo) {
    __nv_bfloat16 h0 = __float2bfloat16_rn(v0);
    __nv_bfloat16 h1 = __float2bfloat16_rn(v1);
    __nv_bfloat16 l0 = __float2bfloat16_rn(v0 - __bfloat162float(h0));
    __nv_bfloat16 l1 = __float2bfloat16_rn(v1 - __bfloat162float(h1));
    __nv_bfloat162 ph = {h0, h1}, pl = {l0, l1};
    hi = *(uint32_t*)&ph;
    lo = *(uint32_t*)&pl;
}

// Degree histogram
__global__ void count_deg_kernel(const int* __restrict__ col, int* __restrict__ deg, int e) {
    int i = blockIdx.x * blockDim.x + threadIdx.x;
    if (i < e) atomicAdd(&deg[col[i]], 1);
}

// ---------------------------------------------------------------------------
// scan1: per-block (1024 elems) degree totals; also computes dis = rsqrt(deg+1)
// ---------------------------------------------------------------------------
__global__ void __launch_bounds__(256)
scan1_kernel(const int* __restrict__ deg, int* __restrict__ blocksum,
             float* __restrict__ dis, int n) {
    __shared__ int wsum[8];
    int t = threadIdx.x, b = blockIdx.x;
    int base = b * 1024 + t * 4;
    int s = 0;
#pragma unroll
    for (int j = 0; j < 4; j++) {
        int idx = base + j;
        int d = (idx < n) ? deg[idx] : 0;
        s += d;
        if (idx < n) dis[idx] = rsqrtf((float)d + 1.0f);
    }
#pragma unroll
    for (int o = 16; o > 0; o >>= 1) s += __shfl_down_sync(0xffffffffu, s, o);
    if ((t & 31) == 0) wsum[t >> 5] = s;
    __syncthreads();
    if (t == 0) {
        int tot = 0;
#pragma unroll
        for (int w = 0; w < 8; w++) tot += wsum[w];
        blocksum[b] = tot;
    }
}

// ---------------------------------------------------------------------------
// scan3: per-block exclusive scan; block offset via parallel reduce of the
// (<=64) block sums.
// ---------------------------------------------------------------------------
__global__ void __launch_bounds__(256)
scan3_kernel(const int* __restrict__ deg, const int* __restrict__ blocksum,
             int* __restrict__ starts, int* __restrict__ cursor, int n, int nblk) {
    __shared__ int wtot[8];
    __shared__ int sh_off[2];
    __shared__ int sh_tot[2];
    int t = threadIdx.x, b = blockIdx.x;
    int lane = t & 31, wid = t >> 5;

    if (t < 64) {
        int v = (t < nblk) ? blocksum[t] : 0;
        int voff = (t < b) ? v : 0;
#pragma unroll
        for (int o = 16; o > 0; o >>= 1) {
            voff += __shfl_down_sync(0xffffffffu, voff, o);
            v    += __shfl_down_sync(0xffffffffu, v, o);
        }
        if (lane == 0) { sh_off[wid] = voff; sh_tot[wid] = v; }
    }

    int base = b * 1024 + t * 4;
    int v4[4];
#pragma unroll
    for (int j = 0; j < 4; j++) {
        int idx = base + j;
        v4[j] = (idx < n) ? deg[idx] : 0;
    }
    int tsum = v4[0] + v4[1] + v4[2] + v4[3];
    int incl = tsum;
#pragma unroll
    for (int o = 1; o < 32; o <<= 1) {
        int u = __shfl_up_sync(0xffffffffu, incl, o);
        if (lane >= o) incl += u;
    }
    if (lane == 31) wtot[wid] = incl;
    __syncthreads();

    int boff = sh_off[0] + sh_off[1];
    if (b == nblk - 1 && t == 0) starts[n] = sh_tot[0] + sh_tot[1];

    int woff = 0;
#pragma unroll
    for (int w = 0; w < 8; w++) woff += (w < wid) ? wtot[w] : 0;
    int excl = boff + woff + incl - tsum;
#pragma unroll
    for (int j = 0; j < 4; j++) {
        int idx = base + j;
        if (idx < n) { starts[idx] = excl; cursor[idx] = excl; }
        excl += v4[j];
    }
}

// CSR fill
__global__ void fill_kernel(const int* __restrict__ row, const int* __restrict__ col,
                            int* __restrict__ cursor, int* __restrict__ csr_row, int e) {
    int i = blockIdx.x * blockDim.x + threadIdx.x;
    if (i < e) {
        int slot = atomicAdd(&cursor[col[i]], 1);
        csr_row[slot] = row[i];
    }
}

// ---------------------------------------------------------------------------
// Tensor-core GEMM via split-bf16 (3xBF16 ~ fp32 precision):
//   out[N, F] = (x[N, 128] @ W[128, F]) * dis[row]
//
// Occupancy-oriented tiling: BM=64 rows, 8 warps; warp w handles the
// 16-row slab (w>>1) and column half (w&1)*F/2. acc = NT*4 = F/4 regs
// (32 for F=128), __launch_bounds__(256, 3) -> 3 CTAs/SM (37.5% occ).
// smem 53KB (F=128) / 37KB (F=64) fits 3 CTAs.
// ---------------------------------------------------------------------------
template <int F>
__global__ void __launch_bounds__(256, 3)
gemm_tc_kernel(const float* __restrict__ x, const float* __restrict__ W,
               float* __restrict__ out, const float* __restrict__ dis, int nrows) {
    constexpr int BM   = 64;
    constexpr int KT   = 64;
    constexpr int NT   = F / 16;         // 8-col tiles per warp (covers F/2)
    constexpr int ASTR = KT + 8;         // 72
    constexpr int WSTR = F + 8;

    extern __shared__ __nv_bfloat16 smem[];
    __nv_bfloat16* Ahi = smem;                    // [BM][ASTR]
    __nv_bfloat16* Alo = Ahi + BM * ASTR;
    __nv_bfloat16* Whi = Alo + BM * ASTR;         // [KT][WSTR]
    __nv_bfloat16* Wlo = Whi + KT * WSTR;

    const int tid  = threadIdx.x;
    const int lane = tid & 31;
    const int w    = tid >> 5;           // warp 0..7
    const int slab = w >> 1;             // 16-row slab 0..3
    const int ch   = w & 1;              // column half
    const int row0 = blockIdx.x * BM;

    float acc[NT][4];
#pragma unroll
    for (int nt = 0; nt < NT; nt++)
#pragma unroll
        for (int j = 0; j < 4; j++) acc[nt][j] = 0.f;

    const int mat  = lane >> 3;
    const int mrow = lane & 7;

    for (int kt = 0; kt < FIN; kt += KT) {
        // ---- A tile: BM x KT fp32 -> hi/lo bf16 ----
        {
            constexpr int NV = (BM * KT) / 4;    // 1024
#pragma unroll
            for (int p = tid; p < NV; p += 256) {
                int r  = p / (KT / 4);
                int kq = (p % (KT / 4)) * 4;
                float4 v;
                int grow = row0 + r;
                if (grow < nrows)
                    v = *(const float4*)(x + (size_t)grow * FIN + kt + kq);
                else
                    v = make_float4(0.f, 0.f, 0.f, 0.f);
                uint32_t h01, l01, h23, l23;
                split2(v.x, v.y, h01, l01);
                split2(v.z, v.w, h23, l23);
                *(uint32_t*)(Ahi + r * ASTR + kq)     = h01;
                *(uint32_t*)(Ahi + r * ASTR + kq + 2) = h23;
                *(uint32_t*)(Alo + r * ASTR + kq)     = l01;
                *(uint32_t*)(Alo + r * ASTR + kq + 2) = l23;
            }
        }
        // ---- W tile: KT x F fp32 -> hi/lo bf16 ----
        {
            constexpr int NV = (KT * F) / 4;
#pragma unroll
            for (int p = tid; p < NV; p += 256) {
                int k = p / (F / 4);
                int c = (p % (F / 4)) * 4;
                float4 v = *(const float4*)(W + (size_t)(kt + k) * F + c);
                uint32_t h01, l01, h23, l23;
                split2(v.x, v.y, h01, l01);
                split2(v.z, v.w, h23, l23);
                *(uint32_t*)(Whi + k * WSTR + c)     = h01;
                *(uint32_t*)(Whi + k * WSTR + c + 2) = h23;
                *(uint32_t*)(Wlo + k * WSTR + c)     = l01;
                *(uint32_t*)(Wlo + k * WSTR + c + 2) = l23;
            }
        }
        __syncthreads();

#pragma unroll
        for (int ks = 0; ks < KT / 16; ks++) {
            uint32_t ah[4], al[4];
            {
                int arow = slab * 16 + (mat & 1) * 8 + mrow;
                int acol = ks * 16 + (mat >> 1) * 8;
                uint32_t a_hi = smem_u32(Ahi + arow * ASTR + acol);
                uint32_t a_lo = smem_u32(Alo + arow * ASTR + acol);
                ldmat_x4(ah[0], ah[1], ah[2], ah[3], a_hi);
                ldmat_x4(al[0], al[1], al[2], al[3], a_lo);
            }
#pragma unroll
            for (int nt2 = 0; nt2 < NT / 2; nt2++) {
                int krow = ks * 16 + (mat & 1) * 8 + mrow;
                int ncol = ch * (F / 2) + nt2 * 16 + (mat >> 1) * 8;
                uint32_t w_hi = smem_u32(Whi + krow * WSTR + ncol);
                uint32_t w_lo = smem_u32(Wlo + krow * WSTR + ncol);
                uint32_t bh[4], bl[4];
                ldmat_x4_t(bh[0], bh[1], bh[2], bh[3], w_hi);
                ldmat_x4_t(bl[0], bl[1], bl[2], bl[3], w_lo);
                mma_bf16(acc[2 * nt2], ah, bh[0], bh[1]);
                mma_bf16(acc[2 * nt2], ah, bl[0], bl[1]);
                mma_bf16(acc[2 * nt2], al, bh[0], bh[1]);
                mma_bf16(acc[2 * nt2 + 1], ah, bh[2], bh[3]);
                mma_bf16(acc[2 * nt2 + 1], ah, bl[2], bl[3]);
                mma_bf16(acc[2 * nt2 + 1], al, bh[2], bh[3]);
            }
        }
        __syncthreads();
    }

    // ---- epilogue: scale by dis[row], write f32 ----
    {
        int r0 = row0 + slab * 16 + (lane >> 2);
        int r1 = r0 + 8;
        float s0 = (r0 < nrows) ? __ldg(dis + r0) : 0.f;
        float s1 = (r1 < nrows) ? __ldg(dis + r1) : 0.f;
        int cbase = ch * (F / 2) + (lane & 3) * 2;
#pragma unroll
        for (int nt = 0; nt < NT; nt++) {
            int c = cbase + nt * 8;
            if (r0 < nrows)
                *(float2*)(out + (size_t)r0 * F + c) = make_float2(acc[nt][0] * s0, acc[nt][1] * s0);
            if (r1 < nrows)
                *(float2*)(out + (size_t)r1 * F + c) = make_float2(acc[nt][2] * s1, acc[nt][3] * s1);
        }
    }
}

// ---------------------------------------------------------------------------
// CSR segment-sum aggregate (hs already scaled by dis[row]); 4-way ILP:
//   out[c] = act( dis[c] * ( hs[c] + sum_e hs[row_e] ) + bias )
// ---------------------------------------------------------------------------
template <int F, bool RELU>
__global__ void __launch_bounds__(256)
aggregate_kernel(const float* __restrict__ hs,
                 const int* __restrict__ csr_row, const int* __restrict__ starts,
                 const float* __restrict__ dis, const float* __restrict__ bias,
                 float* __restrict__ out, int n) {
    constexpr int LPN = F / 4;
    const int gtid = blockIdx.x * blockDim.x + threadIdx.x;
    const int node = gtid / LPN;
    const int sub  = gtid % LPN;
    if (node >= n) return;

    const int beg = __ldg(starts + node);
    const int end = __ldg(starts + node + 1);

    float4 a0 = *(const float4*)(hs + (size_t)node * F + sub * 4);  // self loop
    float4 a1 = make_float4(0.f, 0.f, 0.f, 0.f);
    float4 a2 = make_float4(0.f, 0.f, 0.f, 0.f);
    float4 a3 = make_float4(0.f, 0.f, 0.f, 0.f);

    int e = beg;
    for (; e + 3 < end; e += 4) {
        int r0 = __ldg(csr_row + e);
        int r1 = __ldg(csr_row + e + 1);
        int r2 = __ldg(csr_row + e + 2);
        int r3 = __ldg(csr_row + e + 3);
        float4 v0 = *(const float4*)(hs + (size_t)r0 * F + sub * 4);
        float4 v1 = *(const float4*)(hs + (size_t)r1 * F + sub * 4);
        float4 v2 = *(const float4*)(hs + (size_t)r2 * F + sub * 4);
        float4 v3 = *(const float4*)(hs + (size_t)r3 * F + sub * 4);
        a0.x += v0.x; a0.y += v0.y; a0.z += v0.z; a0.w += v0.w;
        a1.x += v1.x; a1.y += v1.y; a1.z += v1.z; a1.w += v1.w;
        a2.x += v2.x; a2.y += v2.y; a2.z += v2.z; a2.w += v2.w;
        a3.x += v3.x; a3.y += v3.y; a3.z += v3.z; a3.w += v3.w;
    }
    for (; e < end; e++) {
        int r0 = __ldg(csr_row + e);
        float4 v0 = *(const float4*)(hs + (size_t)r0 * F + sub * 4);
        a0.x += v0.x; a0.y += v0.y; a0.z += v0.z; a0.w += v0.w;
    }

    const float d = __ldg(dis + node);
    float4 bv = *(const float4*)(bias + sub * 4);
    float4 o;
    o.x = (a0.x + a1.x + a2.x + a3.x) * d + bv.x;
    o.y = (a0.y + a1.y + a2.y + a3.y) * d + bv.y;
    o.z = (a0.z + a1.z + a2.z + a3.z) * d + bv.z;
    o.w = (a0.w + a1.w + a2.w + a3.w) * d + bv.w;
    if (RELU) {
        o.x = fmaxf(o.x, 0.f); o.y = fmaxf(o.y, 0.f);
        o.z = fmaxf(o.z, 0.f); o.w = fmaxf(o.w, 0.f);
    }
    *(float4*)(out + (size_t)node * F + sub * 4) = o;
}

// ---------------------------------------------------------------------------
// Launch (single stream, sequential — streams measured as a net loss)
// ---------------------------------------------------------------------------
extern "C" void kernel_launch(void* const* d_in, const int* in_sizes, int n_in,
                              void* d_out, int out_size) {
    const float* x  = (const float*)d_in[0];
    const int*   ei = (const int*)d_in[1];
    const float* W1 = (const float*)d_in[2];
    const float* b1 = (const float*)d_in[3];
    const float* W2 = (const float*)d_in[4];
    const float* b2 = (const float*)d_in[5];
    float* out = (float*)d_out;

    const int* row = ei;
    const int* col = ei + EE;

    // smem: A(hi+lo) 64x72 + W(hi+lo) 64x(F+8), bf16
    constexpr int SMEM1 = (64 * 72 * 2 + 64 * 136 * 2) * 2;  // 53,248 B (F=128)
    constexpr int SMEM2 = (64 * 72 * 2 + 64 * 72 * 2) * 2;   // 36,864 B (F=64)

    static float *p_h = nullptr, *p_agg = nullptr, *p_h2 = nullptr, *p_dis = nullptr;
    static int *p_deg = nullptr, *p_starts = nullptr, *p_cursor = nullptr,
               *p_csr = nullptr, *p_bsum = nullptr;
    if (!p_h) {
        cudaGetSymbolAddress((void**)&p_h,      g_h);
        cudaGetSymbolAddress((void**)&p_agg,    g_agg);
        cudaGetSymbolAddress((void**)&p_h2,     g_h2);
        cudaGetSymbolAddress((void**)&p_dis,    g_dis);
        cudaGetSymbolAddress((void**)&p_deg,    g_deg);
        cudaGetSymbolAddress((void**)&p_starts, g_starts);
        cudaGetSymbolAddress((void**)&p_cursor, g_cursor);
        cudaGetSymbolAddress((void**)&p_csr,    g_csr_row);
        cudaGetSymbolAddress((void**)&p_bsum,   g_blocksum);
        cudaFuncSetAttribute(gemm_tc_kernel<128>,
                             cudaFuncAttributeMaxDynamicSharedMemorySize, SMEM1);
        cudaFuncSetAttribute(gemm_tc_kernel<64>,
                             cudaFuncAttributeMaxDynamicSharedMemorySize, SMEM2);
    }

    const int NBLK = (NN + 1023) / 1024;   // 49
    const int GBLK = (NN + 63) / 64;       // 782

    // ---- degree + dis + CSR build ----
    cudaMemsetAsync(p_deg, 0, (size_t)NN * sizeof(int), 0);
    count_deg_kernel<<<(EE + 255) / 256, 256>>>(col, p_deg, EE);
    scan1_kernel<<<NBLK, 256>>>(p_deg, p_bsum, p_dis, NN);
    scan3_kernel<<<NBLK, 256>>>(p_deg, p_bsum, p_starts, p_cursor, NN, NBLK);
    fill_kernel<<<(EE + 255) / 256, 256>>>(row, col, p_cursor, p_csr, EE);

    // ---- layer 1: tensor GEMM (hs1 = (x@W1)*dis) ----
    gemm_tc_kernel<128><<<GBLK, 256, SMEM1>>>(x, W1, p_h, p_dis, NN);

    // ---- layer 1 aggregate -> g_agg = h ----
    {
        long long threads = (long long)NN * 32;
        aggregate_kernel<128, true><<<(int)((threads + 255) / 256), 256>>>(
            p_h, p_csr, p_starts, p_dis, b1, p_agg, NN);
    }

    // ---- layer 2: tensor GEMM (hs2 = (h@W2)*dis) ----
    gemm_tc_kernel<64><<<GBLK, 256, SMEM2>>>(p_agg, W2, p_h2, p_dis, NN);

    // ---- layer 2 aggregate -> d_out ----
    {
        long long threads = (long long)NN * 16;
        aggregate_kernel<64, false><<<(int)((threads + 255) / 256), 256>>>(
            p_h2, p_csr, p_starts, p_dis, b2, out, NN);
    }
}